// round 13
// baseline (speedup 1.0000x reference)
#include <cuda_runtime.h>
#include <cuda_bf16.h>
#include <cstdint>

#if defined(__CUDA_ARCH_FEAT_SM103_ALL) || defined(__CUDA_ARCH_FEAT_SM100_ALL) || \
    defined(__CUDA_ARCH_FEAT_SM101_ALL)
#define TC_OK 1
#else
#define TC_OK 0
#endif

namespace cfg {
constexpr int B  = 4;
constexpr int S  = 2048;
constexpr int D  = 768;
constexpr int H  = 12;
constexpr int HD = 64;
constexpr int MTOK = B * S;       // 8192
constexpr int NQKV = 3 * D;       // 2304
constexpr int BH   = B * H;       // 48
}

// -------- scratch: everything bf16 hi/lo 2-term split --------
__device__ __nv_bfloat16 g_Qh [(size_t)cfg::BH * cfg::S * cfg::HD];
__device__ __nv_bfloat16 g_Ql [(size_t)cfg::BH * cfg::S * cfg::HD];
__device__ __nv_bfloat16 g_Kh [(size_t)cfg::BH * cfg::S * cfg::HD];
__device__ __nv_bfloat16 g_Kl [(size_t)cfg::BH * cfg::S * cfg::HD];
__device__ __nv_bfloat16 g_Vh [(size_t)cfg::BH * cfg::S * cfg::HD];  // [bh][s][d]
__device__ __nv_bfloat16 g_Vl [(size_t)cfg::BH * cfg::S * cfg::HD];
__device__ __nv_bfloat16 g_VTh[(size_t)cfg::BH * cfg::HD * cfg::S];  // [bh][d][s]
__device__ __nv_bfloat16 g_VTl[(size_t)cfg::BH * cfg::HD * cfg::S];
__device__ float         g_SV [(size_t)cfg::BH * cfg::HD * cfg::S];  // fp32 suffix sums
__device__ __nv_bfloat16 g_Ah [(size_t)cfg::MTOK * cfg::D];
__device__ __nv_bfloat16 g_Al [(size_t)cfg::MTOK * cfg::D];
__device__ __nv_bfloat16 g_Xh [(size_t)cfg::MTOK * cfg::D];
__device__ __nv_bfloat16 g_Xl [(size_t)cfg::MTOK * cfg::D];
__device__ __nv_bfloat16 g_WTah[(size_t)cfg::NQKV * cfg::D];
__device__ __nv_bfloat16 g_WTal[(size_t)cfg::NQKV * cfg::D];
__device__ __nv_bfloat16 g_WTph[(size_t)cfg::D * cfg::D];
__device__ __nv_bfloat16 g_WTpl[(size_t)cfg::D * cfg::D];

// ============================================================================
// helpers
// ============================================================================
__device__ __forceinline__ uint32_t smem_to_u32(const void* p) {
    uint32_t a;
    asm("{ .reg .u64 t; cvta.to.shared.u64 t, %1; cvt.u32.u64 %0, t; }"
        : "=r"(a) : "l"(p));
    return a;
}

__device__ __forceinline__ uint32_t pk_bf2(float a, float b) {
    __nv_bfloat162 t;
    t.x = __float2bfloat16(a);
    t.y = __float2bfloat16(b);
    return *(uint32_t*)&t;
}
__device__ __forceinline__ float2 upk_bf2(uint32_t u) {
    __nv_bfloat162 t = *(__nv_bfloat162*)&u;
    return make_float2(__bfloat162float(t.x), __bfloat162float(t.y));
}

#define SMEM_SWIZZLE_128B(off) ((off) ^ (((off) >> 3) & 0x70))
// bf16 tiles all have exactly 128-byte rows: plain 8-row SW128 atoms
__device__ __forceinline__ uint32_t bf_off(int row, int colb) {
    return SMEM_SWIZZLE_128B((uint32_t)(row * 128 + colb));
}

#if TC_OK
__device__ __forceinline__ uint32_t elect_one_pred() {
    uint32_t pred;
    asm volatile(
        "{\n\t.reg .pred p;\n\telect.sync _|p, 0xFFFFFFFF;\n\t"
        "selp.b32 %0, 1, 0, p;\n\t}"
        : "=r"(pred));
    return pred;
}

#define TCGEN05_ALLOC(a, n) \
    asm volatile("tcgen05.alloc.cta_group::1.sync.aligned.shared::cta.b32 [%0], %1;" \
                 :: "r"((uint32_t)(a)), "r"((uint32_t)(n)) : "memory")
#define TCGEN05_DEALLOC(t, n) \
    asm volatile("tcgen05.dealloc.cta_group::1.sync.aligned.b32 %0, %1;" \
                 :: "r"(t), "r"((uint32_t)(n)))
#define TCGEN05_RELINQUISH() \
    asm volatile("tcgen05.relinquish_alloc_permit.cta_group::1.sync.aligned;")
#define TCGEN05_COMMIT(m) \
    asm volatile("tcgen05.commit.cta_group::1.mbarrier::arrive::one.shared::cluster.b64 [%0];" \
                 :: "r"((uint32_t)(m)) : "memory")
#define TCGEN05_WAIT_LD() asm volatile("tcgen05.wait::ld.sync.aligned;" ::: "memory")
#define TCGEN05_WAIT_ST() asm volatile("tcgen05.wait::st.sync.aligned;" ::: "memory")
#define TCGEN05_FENCE_AFTER()  asm volatile("tcgen05.fence::after_thread_sync;" ::: "memory")
#define TCGEN05_FENCE_BEFORE() asm volatile("tcgen05.fence::before_thread_sync;" ::: "memory")
#define FENCE_PROXY_ASYNC() asm volatile("fence.proxy.async.shared::cta;" ::: "memory")

#define MBARRIER_INIT(m, c) \
    asm volatile("mbarrier.init.shared.b64 [%0], %1;" \
                 :: "r"((uint32_t)(m)), "r"((uint32_t)(c)) : "memory")
#define MBARRIER_INVAL(m) \
    asm volatile("mbarrier.inval.shared.b64 [%0];" :: "r"((uint32_t)(m)) : "memory")

#define MBARRIER_WAIT_PARITY(mbar_addr, phase_parity) do { \
    uint32_t _mbar = (uint32_t)(mbar_addr); \
    uint32_t _parity = (uint32_t)(phase_parity); \
    uint32_t _done; \
    asm volatile( \
        "{\n\t.reg .pred p;\n\t" \
        "mbarrier.try_wait.parity.acquire.cta.shared::cta.b64 p, [%1], %2;\n\t" \
        "selp.b32 %0, 1, 0, p;\n\t}" \
        : "=r"(_done) : "r"(_mbar), "r"(_parity) : "memory"); \
    if (!_done) { \
        asm volatile( \
            "{\n\t.reg .pred P1;\n\t" \
            "WAIT_LOOP_%=:\n\t" \
            "mbarrier.try_wait.parity.acquire.cta.shared::cta.b64 P1, [%0], %1, 0x989680;\n\t" \
            "@P1 bra.uni WAIT_DONE_%=;\n\t" \
            "bra.uni WAIT_LOOP_%=;\n\t" \
            "WAIT_DONE_%=:\n\t}" \
            :: "r"(_mbar), "r"(_parity) : "memory"); \
    } \
} while(0)

#define TCGEN05_LD_32X32B_X32(r, tmem_addr) \
    asm volatile( \
        "tcgen05.ld.sync.aligned.32x32b.x32.b32 " \
        "{%0, %1, %2, %3, %4, %5, %6, %7, " \
        " %8, %9, %10, %11, %12, %13, %14, %15, " \
        " %16, %17, %18, %19, %20, %21, %22, %23, " \
        " %24, %25, %26, %27, %28, %29, %30, %31}, [%32];" \
        : "=r"((r)[0]),  "=r"((r)[1]),  "=r"((r)[2]),  "=r"((r)[3]), \
          "=r"((r)[4]),  "=r"((r)[5]),  "=r"((r)[6]),  "=r"((r)[7]), \
          "=r"((r)[8]),  "=r"((r)[9]),  "=r"((r)[10]), "=r"((r)[11]), \
          "=r"((r)[12]), "=r"((r)[13]), "=r"((r)[14]), "=r"((r)[15]), \
          "=r"((r)[16]), "=r"((r)[17]), "=r"((r)[18]), "=r"((r)[19]), \
          "=r"((r)[20]), "=r"((r)[21]), "=r"((r)[22]), "=r"((r)[23]), \
          "=r"((r)[24]), "=r"((r)[25]), "=r"((r)[26]), "=r"((r)[27]), \
          "=r"((r)[28]), "=r"((r)[29]), "=r"((r)[30]), "=r"((r)[31]) \
        : "r"(tmem_addr))

#define TCGEN05_ST_32X32B_X16(tmem_addr, r) \
    asm volatile( \
        "tcgen05.st.sync.aligned.32x32b.x16.b32 [%0], " \
        "{%1, %2, %3, %4, %5, %6, %7, %8, " \
        " %9, %10, %11, %12, %13, %14, %15, %16};" \
        :: "r"(tmem_addr), \
           "r"((r)[0]),  "r"((r)[1]),  "r"((r)[2]),  "r"((r)[3]), \
           "r"((r)[4]),  "r"((r)[5]),  "r"((r)[6]),  "r"((r)[7]), \
           "r"((r)[8]),  "r"((r)[9]),  "r"((r)[10]), "r"((r)[11]), \
           "r"((r)[12]), "r"((r)[13]), "r"((r)[14]), "r"((r)[15]) \
        : "memory")

static constexpr uint64_t SMEM_DESC_BASE_SW128 =
    (uint64_t(2)  << 61) | (uint64_t(1) << 46) | (uint64_t(64) << 32) | (uint64_t(1) << 16);
#define MAKE_SMEM_DESC(base_addr) \
    (SMEM_DESC_BASE_SW128 | ((uint64_t)((base_addr) >> 4) & 0x3FFF))

// bf16 MMA, kind::f16 (atype=btype=BF16), fp32 accum
__device__ __forceinline__ void mma_bf16_ss(uint32_t d, uint64_t ad, uint64_t bd,
                                            uint32_t idesc, bool acc) {
    uint32_t en = acc ? 1u : 0u;
    asm volatile(
        "{\n\t.reg .pred p;\n\tsetp.ne.u32 p, %5, 0;\n\t"
        "tcgen05.mma.cta_group::1.kind::f16 [%0], %1, %2, %3, {%4, %4, %4, %4}, p;\n\t}"
        :: "r"(d), "l"(ad), "l"(bd), "r"(idesc), "r"(0u), "r"(en)
        : "memory");
}
__device__ __forceinline__ void mma_bf16_ts(uint32_t d, uint32_t a_tmem, uint64_t bd,
                                            uint32_t idesc, bool acc) {
    uint32_t en = acc ? 1u : 0u;
    asm volatile(
        "{\n\t.reg .pred p;\n\tsetp.ne.u32 p, %5, 0;\n\t"
        "tcgen05.mma.cta_group::1.kind::f16 [%0], [%1], %2, %3, {%4, %4, %4, %4}, p;\n\t}"
        :: "r"(d), "r"(a_tmem), "l"(bd), "r"(idesc), "r"(0u), "r"(en)
        : "memory");
}

// idesc kind::f16: c=F32(1@4), a=BF16(1@7), b=BF16(1@10), N@17 (N/8), M@24 (M/16)
static constexpr uint32_t IDESC_BF16_128x128 =
    (1u << 4) | (1u << 7) | (1u << 10) | ((128u / 8u) << 17) | ((128u / 16u) << 24);
static constexpr uint32_t IDESC_BF16_128x64 =
    (1u << 4) | (1u << 7) | (1u << 10) | ((64u / 8u) << 17) | ((128u / 16u) << 24);

#define CP_ASYNC16(dst, src) \
    asm volatile("cp.async.cg.shared.global [%0], [%1], 16;" \
                 :: "r"((uint32_t)(dst)), "l"(src) : "memory")
#define CP_COMMIT() asm volatile("cp.async.commit_group;" ::: "memory")
#define CP_WAIT(n)  asm volatile("cp.async.wait_group %0;" :: "n"(n) : "memory")
#endif  // TC_OK

// ============================================================================
// prep: elementwise bf16 hi/lo split of x
// ============================================================================
__global__ void __launch_bounds__(256) split_x_kernel(const float* __restrict__ x)
{
    int i = blockIdx.x * 256 + threadIdx.x;        // 4-element group
    if (i >= cfg::MTOK * cfg::D / 4) return;
    float4 v = ((const float4*)x)[i];
    float h0 = __bfloat162float(__float2bfloat16(v.x));
    float h1 = __bfloat162float(__float2bfloat16(v.y));
    float h2 = __bfloat162float(__float2bfloat16(v.z));
    float h3 = __bfloat162float(__float2bfloat16(v.w));
    uint32_t* ph = (uint32_t*)g_Xh;
    uint32_t* pl = (uint32_t*)g_Xl;
    ph[i * 2 + 0] = pk_bf2(h0, h1);
    ph[i * 2 + 1] = pk_bf2(h2, h3);
    pl[i * 2 + 0] = pk_bf2(v.x - h0, v.y - h1);
    pl[i * 2 + 1] = pk_bf2(v.z - h2, v.w - h3);
}

// ============================================================================
// prep: transpose + bf16 split weights
// ============================================================================
__global__ void transpose_split_kernel(const float* __restrict__ in,
                                       __nv_bfloat16* __restrict__ outh,
                                       __nv_bfloat16* __restrict__ outl, int R, int C)
{
    __shared__ float t[32][33];
    int bx = blockIdx.x * 32;
    int by = blockIdx.y * 32;
    int x = bx + threadIdx.x;
#pragma unroll
    for (int j = 0; j < 32; j += 8)
        t[threadIdx.y + j][threadIdx.x] = in[(size_t)(by + threadIdx.y + j) * C + x];
    __syncthreads();
    int x2 = by + threadIdx.x;
#pragma unroll
    for (int j = 0; j < 32; j += 8) {
        float v = t[threadIdx.x][threadIdx.y + j];
        __nv_bfloat16 h = __float2bfloat16(v);
        outh[(size_t)(bx + threadIdx.y + j) * R + x2] = h;
        outl[(size_t)(bx + threadIdx.y + j) * R + x2] =
            __float2bfloat16(v - __bfloat162float(h));
    }
}

// ============================================================================
// V transpose (bf16): g_Vh/g_Vl [bh][s][64] -> g_VTh/g_VTl [bh][d][2048]
// ============================================================================
__global__ void vt_kernel()
{
    __shared__ uint16_t th[32][33], tl[32][33];
    const int bh   = blockIdx.x;
    const int tile = blockIdx.y;
    const int s0 = (tile >> 1) * 32;
    const int d0 = (tile & 1) * 32;
    const size_t vb  = (size_t)bh * cfg::S * cfg::HD;
    const size_t vtb = (size_t)bh * cfg::HD * cfg::S;
#pragma unroll
    for (int j = 0; j < 32; j += 8) {
        size_t off = vb + (size_t)(s0 + threadIdx.y + j) * 64 + d0 + threadIdx.x;
        th[threadIdx.y + j][threadIdx.x] = *(const uint16_t*)&g_Vh[off];
        tl[threadIdx.y + j][threadIdx.x] = *(const uint16_t*)&g_Vl[off];
    }
    __syncthreads();
#pragma unroll
    for (int j = 0; j < 32; j += 8) {
        size_t off = vtb + (size_t)(d0 + threadIdx.y + j) * 2048 + s0 + threadIdx.x;
        *(uint16_t*)&g_VTh[off] = th[threadIdx.x][threadIdx.y + j];
        *(uint16_t*)&g_VTl[off] = tl[threadIdx.x][threadIdx.y + j];
    }
}

// ============================================================================
// GEMM (bf16 2-term): C = (Ah+Al)[M,K] @ (Bh+Bl)[N,K]^T + bias
// 128x128 tile, BK=32, hi|lo chunks INTERLEAVED in one 128B SW128 row
// (cols 0..31 = hi, 32..63 = lo) -> 32KB/stage, 3 stages = 96KB -> 2 CTAs/SM.
// Al descriptor = desc(A)+4 (64B); k-steps at +0,+2 (proven SW128 pattern).
// ============================================================================
constexpr int G3_BASE  = 1024;
constexpr int G3_STAGE = 32768;                       // A-tile 16KB + B-tile 16KB
constexpr int G3_SMEM  = G3_BASE + 3 * G3_STAGE;      // 99328 -> 2 CTAs/SM

template<bool SCATTER>
__global__ void __launch_bounds__(256) gemm_bf16_kernel(
    const __nv_bfloat16* __restrict__ Ah, const __nv_bfloat16* __restrict__ Al,
    const __nv_bfloat16* __restrict__ Bh, const __nv_bfloat16* __restrict__ Bl,
    const float* __restrict__ bias, float* __restrict__ C,
    int M, int N, int K)
{
    extern __shared__ char smem[];
    const int tid = threadIdx.x;
    const int m0  = blockIdx.y * 128;
    const int n0  = blockIdx.x * 128;

#if TC_OK
    const uint32_t smem_base = smem_to_u32(smem);
    const int wid = tid >> 5;
    const int lid = tid & 31;

    if (wid == 0) TCGEN05_ALLOC(smem_base, 128);
    if (tid == 0) {
        MBARRIER_INIT(smem_base + 16, 1);
        MBARRIER_INIT(smem_base + 24, 1);
        MBARRIER_INIT(smem_base + 32, 1);
    }
    __syncthreads();
    uint32_t tmem;
    asm volatile("ld.shared.b32 %0, [%1];" : "=r"(tmem) : "r"(smem_base));

    const int T = K / 32;    // 24
    int ph[3] = {0, 0, 0};

    // loader: 2 groups/thread; each group fills one 16B chunk of all 4 sources.
    // A-tile row layout: [hi bf16 0..31 | lo bf16 0..31] = 128B.
    uint32_t offh[2], offl[2];
    const __nv_bfloat16 *pAh[2], *pAl[2], *pBh[2], *pBl[2];
#pragma unroll
    for (int i = 0; i < 2; i++) {
        int g   = tid + i * 256;
        int row = g >> 2;          // 0..127
        int c   = g & 3;           // 16B chunk within 64B half
        offh[i] = bf_off(row, c * 16);
        offl[i] = bf_off(row, 64 + c * 16);
        pAh[i] = Ah + (size_t)(m0 + row) * K + c * 8;
        pAl[i] = Al + (size_t)(m0 + row) * K + c * 8;
        pBh[i] = Bh + (size_t)(n0 + row) * K + c * 8;
        pBl[i] = Bl + (size_t)(n0 + row) * K + c * 8;
    }

    auto cp_tile = [&](uint32_t stage) {
#pragma unroll
        for (int i = 0; i < 2; i++) {
            CP_ASYNC16(stage + offh[i],         pAh[i]);
            CP_ASYNC16(stage + offl[i],         pAl[i]);
            CP_ASYNC16(stage + 16384 + offh[i], pBh[i]);
            CP_ASYNC16(stage + 16384 + offl[i], pBl[i]);
            pAh[i] += 32; pAl[i] += 32; pBh[i] += 32; pBl[i] += 32;
        }
        CP_COMMIT();
    };

    cp_tile(smem_base + G3_BASE);
    cp_tile(smem_base + G3_BASE + G3_STAGE);

    for (int t = 0; t < T; t++) {
        const int s = t % 3;
        const uint32_t stage = smem_base + G3_BASE + s * G3_STAGE;

        if (t == T - 1) CP_WAIT(0); else CP_WAIT(1);
        __syncthreads();

        if (wid == 0) {
            if (elect_one_pred()) {
                FENCE_PROXY_ASYNC();
                uint64_t dA = MAKE_SMEM_DESC(stage);
                uint64_t dB = MAKE_SMEM_DESC(stage + 16384);
#pragma unroll
                for (int j = 0; j < 2; j++) {      // K-steps of 16 bf16 (32B)
                    uint64_t oj = (uint64_t)(j * 2);
                    mma_bf16_ss(tmem, dA + oj,     dB + oj,     IDESC_BF16_128x128,
                                !(t == 0 && j == 0));
                    mma_bf16_ss(tmem, dA + 4 + oj, dB + oj,     IDESC_BF16_128x128, true);
                    mma_bf16_ss(tmem, dA + oj,     dB + 4 + oj, IDESC_BF16_128x128, true);
                }
                TCGEN05_COMMIT(smem_base + 16 + 8 * s);
            }
        }

        if (t + 2 < T) {
            const int s2 = (t + 2) % 3;
            if (t >= 1) {
                MBARRIER_WAIT_PARITY(smem_base + 16 + 8 * s2, ph[s2]);
                ph[s2] ^= 1;
            }
            cp_tile(smem_base + G3_BASE + s2 * G3_STAGE);
        }
    }

    {
        const int sl = (T - 1) % 3;
        MBARRIER_WAIT_PARITY(smem_base + 16 + 8 * sl, ph[sl]);
    }
    TCGEN05_FENCE_AFTER();

    float* buf = (float*)(smem + G3_BASE);    // [128][132] = 67.6KB (fits 96KB)
    if (wid < 4) {
#pragma unroll
        for (int b = 0; b < 4; b++) {
            uint32_t regs[32];
            TCGEN05_LD_32X32B_X32(regs, tmem + b * 32);
            TCGEN05_WAIT_LD();
            float* row = buf + (size_t)(wid * 32 + lid) * 132 + b * 32;
#pragma unroll
            for (int c = 0; c < 32; c++) row[c] = __uint_as_float(regs[c]);
        }
        TCGEN05_FENCE_BEFORE();
    }
    __syncthreads();

#pragma unroll
    for (int i = 0; i < 16; i++) {
        int g  = tid + i * 256;
        int rr = g >> 5;
        int c4 = (g & 31) * 4;
        const float* row = buf + (size_t)rr * 132 + c4;
        int n = n0 + c4;
        float4 bv = *(const float4*)(bias + n);
        float v0 = row[0] + bv.x, v1 = row[1] + bv.y;
        float v2 = row[2] + bv.z, v3 = row[3] + bv.w;
        int m = m0 + rr;
        if (!SCATTER) {
            float4 v = {v0, v1, v2, v3};
            *(float4*)(C + (size_t)m * N + n) = v;
        } else {
            float h0 = __bfloat162float(__float2bfloat16(v0));
            float h1 = __bfloat162float(__float2bfloat16(v1));
            float h2 = __bfloat162float(__float2bfloat16(v2));
            float h3 = __bfloat162float(__float2bfloat16(v3));
            int part = n / cfg::D;
            int dn   = n - part * cfg::D;
            int hh   = dn >> 6;
            int c    = dn & 63;
            int b_   = m >> 11;
            int s_   = m & 2047;
            __nv_bfloat16* dsth = (part == 0) ? g_Qh : (part == 1) ? g_Kh : g_Vh;
            __nv_bfloat16* dstl = (part == 0) ? g_Ql : (part == 1) ? g_Kl : g_Vl;
            size_t off = ((size_t)(b_ * cfg::H + hh) * cfg::S + s_) * cfg::HD + c;
            uint32_t* dh = (uint32_t*)(dsth + off);
            uint32_t* dl = (uint32_t*)(dstl + off);
            dh[0] = pk_bf2(v0, v1);
            dh[1] = pk_bf2(v2, v3);
            dl[0] = pk_bf2(v0 - h0, v1 - h1);
            dl[1] = pk_bf2(v2 - h2, v3 - h3);
        }
    }

    __syncthreads();
    if (tid == 0) {
        MBARRIER_INVAL(smem_base + 16);
        MBARRIER_INVAL(smem_base + 24);
        MBARRIER_INVAL(smem_base + 32);
    }
    __syncthreads();
    if (wid == 0) {
        TCGEN05_RELINQUISH();
        TCGEN05_DEALLOC(tmem, 128);
    }

#else
    // fp32 fallback (compile-only): a = Ah+Al etc.
    float* As = (float*)smem;
    float* Bs = As + 8 * 128;
    const int tx = tid & 15;
    const int ty = tid >> 4;
    const int lr = tid >> 1;
    const int lk = (tid & 1) * 4;

    float acc[8][8];
#pragma unroll
    for (int i = 0; i < 8; i++)
#pragma unroll
        for (int j = 0; j < 8; j++) acc[i][j] = 0.f;

    for (int k0 = 0; k0 < K; k0 += 8) {
        __syncthreads();
#pragma unroll
        for (int q = 0; q < 4; q++) {
            size_t ao = (size_t)(m0 + lr) * K + k0 + lk + q;
            size_t bo = (size_t)(n0 + lr) * K + k0 + lk + q;
            As[(lk + q) * 128 + lr] =
                __bfloat162float(Ah[ao]) + __bfloat162float(Al[ao]);
            Bs[(lk + q) * 128 + lr] =
                __bfloat162float(Bh[bo]) + __bfloat162float(Bl[bo]);
        }
        __syncthreads();
#pragma unroll
        for (int kk = 0; kk < 8; kk++) {
            float a[8], b[8];
#pragma unroll
            for (int i = 0; i < 4; i++) {
                a[i]     = As[kk * 128 + ty * 4 + i];
                a[i + 4] = As[kk * 128 + 64 + ty * 4 + i];
                b[i]     = Bs[kk * 128 + tx * 4 + i];
                b[i + 4] = Bs[kk * 128 + 64 + tx * 4 + i];
            }
#pragma unroll
            for (int i = 0; i < 8; i++)
#pragma unroll
                for (int j = 0; j < 8; j++) acc[i][j] += a[i] * b[j];
        }
    }

#pragma unroll
    for (int i = 0; i < 8; i++) {
        int m = m0 + ((i < 4) ? (ty * 4 + i) : (64 + ty * 4 + (i - 4)));
#pragma unroll
        for (int jh = 0; jh < 2; jh++) {
            int n = n0 + jh * 64 + tx * 4;
            float vv[4];
#pragma unroll
            for (int q = 0; q < 4; q++) vv[q] = acc[i][jh * 4 + q] + bias[n + q];
            if (!SCATTER) {
                float4 v = {vv[0], vv[1], vv[2], vv[3]};
                *(float4*)(C + (size_t)m * N + n) = v;
            } else {
                int part = n / cfg::D;
                int dn   = n - part * cfg::D;
                int hh   = dn >> 6;
                int c    = dn & 63;
                int b_   = m >> 11;
                int s_   = m & 2047;
                __nv_bfloat16* dsth = (part == 0) ? g_Qh : (part == 1) ? g_Kh : g_Vh;
                __nv_bfloat16* dstl = (part == 0) ? g_Ql : (part == 1) ? g_Kl : g_Vl;
                size_t off = ((size_t)(b_ * cfg::H + hh) * cfg::S + s_) * cfg::HD + c;
#pragma unroll
                for (int q = 0; q < 4; q++) {
                    __nv_bfloat16 h = __float2bfloat16(vv[q]);
                    dsth[off + q] = h;
                    dstl[off + q] = __float2bfloat16(vv[q] - __bfloat162float(h));
                }
            }
        }
    }
#endif
}

// ============================================================================
// V suffix sums: SV[bh][d][s] = sum_{k>=s} (VTh+VTl)[bh][d][k], fp32
// ============================================================================
__global__ void __launch_bounds__(256) suffix_kernel()
{
    const int bh  = blockIdx.x;
    const int wid = threadIdx.x >> 5;
    const int lid = threadIdx.x & 31;
    const int d   = blockIdx.y * 8 + wid;
    const size_t rb = ((size_t)bh * 64 + d) * 2048;
    const uint4* vh4 = (const uint4*)(g_VTh + rb);   // 8 bf16 per uint4
    const uint4* vl4 = (const uint4*)(g_VTl + rb);

    float t = 0.f;
#pragma unroll
    for (int i = 0; i < 8; i++) {
        uint4 a = vh4[lid * 8 + i];
        uint4 b = vl4[lid * 8 + i];
        float2 f;
        f = upk_bf2(a.x); t += f.x + f.y;
        f = upk_bf2(a.y); t += f.x + f.y;
        f = upk_bf2(a.z); t += f.x + f.y;
        f = upk_bf2(a.w); t += f.x + f.y;
        f = upk_bf2(b.x); t += f.x + f.y;
        f = upk_bf2(b.y); t += f.x + f.y;
        f = upk_bf2(b.z); t += f.x + f.y;
        f = upk_bf2(b.w); t += f.x + f.y;
    }
    float s = t;
#pragma unroll
    for (int off = 1; off < 32; off <<= 1) {
        float v = __shfl_down_sync(0xffffffffu, s, off);
        if (lid + off < 32) s += v;
    }
    float add = __shfl_down_sync(0xffffffffu, s, 1);
    if (lid == 31) add = 0.f;

    float acc = add;
    float* svp = g_SV + rb + (size_t)lid * 64;
#pragma unroll
    for (int i = 7; i >= 0; i--) {
        uint4 a = vh4[lid * 8 + i];
        uint4 b = vl4[lid * 8 + i];
        float f[8];
        float2 p;
        p = upk_bf2(a.x); f[0] = p.x; f[1] = p.y;
        p = upk_bf2(a.y); f[2] = p.x; f[3] = p.y;
        p = upk_bf2(a.z); f[4] = p.x; f[5] = p.y;
        p = upk_bf2(a.w); f[6] = p.x; f[7] = p.y;
        p = upk_bf2(b.x); f[0] += p.x; f[1] += p.y;
        p = upk_bf2(b.y); f[2] += p.x; f[3] += p.y;
        p = upk_bf2(b.z); f[4] += p.x; f[5] += p.y;
        p = upk_bf2(b.w); f[6] += p.x; f[7] += p.y;
        float r[8];
#pragma unroll
        for (int j = 7; j >= 0; j--) { acc += f[j]; r[j] = acc; }
        float4 w0 = {r[0], r[1], r[2], r[3]};
        float4 w1 = {r[4], r[5], r[6], r[7]};
        *(float4*)(svp + i * 8)     = w0;
        *(float4*)(svp + i * 8 + 4) = w1;
    }
}

// ============================================================================
// Flash attention (bf16 2-term), DELAYED-PV pipeline, 2 CTAs/SM (unchanged
// from R12): fixed-shift softmax, TMEM O accumulator, exact mask via fp32
// suffix sums: out = (o + e*SV[d][q+1])/(li + cnt*e).
// ============================================================================
constexpr int AT_LI   = 128;
constexpr int AT_QH   = 2048;
constexpr int AT_QL   = AT_QH + 16384;
constexpr int AT_K0   = AT_QL + 16384;
constexpr int AT_KSTG = 16384;
constexpr int AT_V0   = AT_K0 + 2 * AT_KSTG;
constexpr int AT_VSTG = 16384;
constexpr int AT_SMEM = AT_V0 + 2 * AT_VSTG;          // 100352

__global__ void __launch_bounds__(256) attn_kernel()
{
    extern __shared__ char smem[];
#if TC_OK
    const uint32_t smem_base = smem_to_u32(smem);
    const uint32_t mbS  = smem_base + 8;
    const uint32_t mbPV = smem_base + 16;
    const int tid  = threadIdx.x;
    const int wid  = tid >> 5;
    const int lid  = tid & 31;
    const int subp = wid & 3;
    const int colw = wid >> 2;
    const uint32_t warp_off = (uint32_t)subp << 21;
    const uint32_t coff = (uint32_t)colw * 32u;

    const int qb = (int)gridDim.x - 1 - (int)blockIdx.x;
    const int bh = blockIdx.y;
    const int b  = bh / cfg::H;
    const int h  = bh % cfg::H;
    const size_t base = (size_t)bh * cfg::S * cfg::HD;
    const size_t vtb  = (size_t)bh * 64 * 2048;

    if (wid == 0) TCGEN05_ALLOC(smem_base, 256);
    if (tid == 0) { MBARRIER_INIT(mbS, 1); MBARRIER_INIT(mbPV, 1); }
    __syncthreads();
    uint32_t tmem;
    asm volatile("ld.shared.b32 %0, [%1];" : "=r"(tmem) : "r"(smem_base));
    const uint32_t T_S  = tmem;
    const uint32_t T_P0 = tmem + 64;
    const uint32_t T_O  = tmem + 192;

    {
        const __nv_bfloat16* Qhg = g_Qh + base + (size_t)qb * 128 * 64;
        const __nv_bfloat16* Qlg = g_Ql + base + (size_t)qb * 128 * 64;
#pragma unroll
        for (int i = 0; i < 4; i++) {
            int g  = tid + i * 256;
            int r  = g >> 3;
            int e8 = (g & 7) * 8;
            uint32_t off = bf_off(r, e8 * 2);
            *(uint4*)(smem + AT_QH + off) = *(const uint4*)(Qhg + (size_t)r * 64 + e8);
            *(uint4*)(smem + AT_QL + off) = *(const uint4*)(Qlg + (size_t)r * 64 + e8);
        }
    }

    auto load_K = [&](int kb, int ks) {
        const int stage = AT_K0 + ks * AT_KSTG;
        const size_t koff = base + (size_t)kb * 64 * 64;
#pragma unroll
        for (int i = 0; i < 2; i++) {
            int g   = tid + i * 256;
            int key = g >> 3;
            int e8  = (g & 7) * 8;
            uint32_t off = bf_off(key, e8 * 2);
            *(uint4*)(smem + stage + off) =
                *(const uint4*)(g_Kh + koff + (size_t)key * 64 + e8);
            *(uint4*)(smem + stage + 8192 + off) =
                *(const uint4*)(g_Kl + koff + (size_t)key * 64 + e8);
        }
    };
    auto load_V = [&](int kb, int vs) {
        const int stage = AT_V0 + vs * AT_VSTG;
        const size_t voff = vtb + (size_t)kb * 64;
#pragma unroll
        for (int i = 0; i < 2; i++) {
            int g  = tid + i * 256;
            int d  = g >> 3;
            int e8 = (g & 7) * 8;
            uint32_t off = bf_off(d, e8 * 2);
            *(uint4*)(smem + stage + off) =
                *(const uint4*)(g_VTh + voff + (size_t)d * 2048 + e8);
            *(uint4*)(smem + stage + 8192 + off) =
                *(const uint4*)(g_VTl + voff + (size_t)d * 2048 + e8);
        }
    };

    const int nkb = 2 * qb + 2;

    auto issue_S = [&](int ks) {
        const uint32_t stage = smem_base + AT_K0 + ks * AT_KSTG;
        uint64_t dqh = MAKE_SMEM_DESC(smem_base + AT_QH);
        uint64_t dql = MAKE_SMEM_DESC(smem_base + AT_QL);
        uint64_t dkh = MAKE_SMEM_DESC(stage);
        uint64_t dkl = MAKE_SMEM_DESC(stage + 8192);
#pragma unroll
        for (int j = 0; j < 4; j++) {
            uint64_t oj = (uint64_t)(j * 2);
            mma_bf16_ss(T_S, dqh + oj, dkh + oj, IDESC_BF16_128x64, j != 0);
            mma_bf16_ss(T_S, dql + oj, dkh + oj, IDESC_BF16_128x64, true);
            mma_bf16_ss(T_S, dqh + oj, dkl + oj, IDESC_BF16_128x64, true);
        }
    };
    auto issue_PV = [&](int pvkb, bool acc) {
        const uint32_t T_PH = T_P0 + (uint32_t)(pvkb & 1) * 64u;
        const uint32_t T_PL = T_PH + 32u;
        const uint32_t stage = smem_base + AT_V0 + (pvkb & 1) * AT_VSTG;
        uint64_t dvh = MAKE_SMEM_DESC(stage);
        uint64_t dvl = MAKE_SMEM_DESC(stage + 8192);
#pragma unroll
        for (int j = 0; j < 4; j++) {
            uint64_t vo = (uint64_t)(j * 2);
            uint32_t ao = (uint32_t)(j * 8);
            mma_bf16_ts(T_O, T_PH + ao, dvh + vo, IDESC_BF16_128x64, acc || j != 0);
            mma_bf16_ts(T_O, T_PL + ao, dvh + vo, IDESC_BF16_128x64, true);
            mma_bf16_ts(T_O, T_PH + ao, dvl + vo, IDESC_BF16_128x64, true);
        }
    };

    load_K(0, 0);
    if (nkb > 1) load_K(1, 1);
    load_V(0, 0);
    __syncthreads();
    if (wid == 0) {
        if (elect_one_pred()) {
            FENCE_PROXY_ASYNC();
            issue_S(0);
            TCGEN05_COMMIT(mbS);
        }
    }

    float li = 0.f;
    const int qg = qb * 128 + subp * 32 + lid;
    int phS = 0, phPV = 0;

    for (int kb = 0; kb < nkb; kb++) {
        MBARRIER_WAIT_PARITY(mbS, phS); phS ^= 1;
        TCGEN05_FENCE_AFTER();

        uint32_t su[32];
        TCGEN05_LD_32X32B_X32(su, T_S + coff + warp_off);
        TCGEN05_WAIT_LD();
        __syncthreads();

        if (wid == 0) {
            TCGEN05_FENCE_AFTER();
            if (elect_one_pred()) {
                FENCE_PROXY_ASYNC();
                if (kb > 0) {
                    issue_PV(kb - 1, kb > 1);
                    TCGEN05_COMMIT(mbPV);
                }
                if (kb + 1 < nkb) {
                    issue_S((kb + 1) & 1);
                    TCGEN05_COMMIT(mbS);
                }
            }
        }

        const uint32_t T_PH = T_P0 + (uint32_t)(kb & 1) * 64u;
        const uint32_t T_PL = T_PH + 32u;
        const int kg0 = kb * 64 + colw * 32;
        const bool diag = (kg0 + 31 > qg);
        float ps = 0.f;
        uint32_t phv[16], plv[16];
#pragma unroll
        for (int j = 0; j < 16; j++) {
            float s0 = __uint_as_float(su[2 * j]);
            float s1 = __uint_as_float(su[2 * j + 1]);
            if (diag) {
                if (kg0 + 2 * j     > qg) s0 = -1e30f;
                if (kg0 + 2 * j + 1 > qg) s1 = -1e30f;
            }
            float p0 = __expf(s0);
            float p1 = __expf(s1);
            ps += p0 + p1;
            float h0 = __bfloat162float(__float2bfloat16(p0));
            float h1 = __bfloat162float(__float2bfloat16(p1));
            phv[j] = pk_bf2(p0, p1);
            plv[j] = pk_bf2(p0 - h0, p1 - h1);
        }
        TCGEN05_ST_32X32B_X16(T_PH + (uint32_t)colw * 16u + warp_off, phv);
        TCGEN05_ST_32X32B_X16(T_PL + (uint32_t)colw * 16u + warp_off, plv);
        TCGEN05_WAIT_ST();
        li += ps;
        TCGEN05_FENCE_BEFORE();

        if (kb + 2 < nkb) load_K(kb + 2, kb & 1);

        if (kb > 0) { MBARRIER_WAIT_PARITY(mbPV, phPV); phPV ^= 1; }
        if (kb + 1 < nkb) load_V(kb + 1, (kb + 1) & 1);
    }

    __syncthreads();
    if (wid == 0) {
        TCGEN05_FENCE_AFTER();
        if (elect_one_pred()) {
            FENCE_PROXY_ASYNC();
            issue_PV(nkb - 1, true);
            TCGEN05_COMMIT(mbPV);
        }
    }
    MBARRIER_WAIT_PARITY(mbPV, phPV);
    TCGEN05_FENCE_AFTER();

    {
        float* sli = (float*)(smem + AT_LI);
        const int rix = subp * 32 + lid;
        sli[rix * 2 + colw] = li;
        __syncthreads();
        float litot = li + sli[rix * 2 + (colw ^ 1)];

        uint32_t ov[32];
        TCGEN05_LD_32X32B_X32(ov, T_O + coff + warp_off);
        TCGEN05_WAIT_LD();

        float e   = __expf(1e-9f);
        float cnt = (float)(cfg::S - 1 - qg);
        float inv = 1.0f / (litot + cnt * e);
        size_t ooff = ((size_t)(b * cfg::S + qg)) * cfg::D + h * cfg::HD + colw * 32;
        const bool has = (qg + 1 < cfg::S);
        uint32_t* oh = (uint32_t*)(g_Ah + ooff);
        uint32_t* ol = (uint32_t*)(g_Al + ooff);
#pragma unroll
        for (int c2 = 0; c2 < 16; c2++) {
            int d0 = colw * 32 + c2 * 2;
            float sv0 = has ? g_SV[vtb + (size_t)(d0 + 0) * 2048 + qg + 1] : 0.f;
            float sv1 = has ? g_SV[vtb + (size_t)(d0 + 1) * 2048 + qg + 1] : 0.f;
            float v0 = (__uint_as_float(ov[c2 * 2])     + e * sv0) * inv;
            float v1 = (__uint_as_float(ov[c2 * 2 + 1]) + e * sv1) * inv;
            float h0 = __bfloat162float(__float2bfloat16(v0));
            float h1 = __bfloat162float(__float2bfloat16(v1));
            oh[c2] = pk_bf2(v0, v1);
            ol[c2] = pk_bf2(v0 - h0, v1 - h1);
        }
    }

    __syncthreads();
    if (tid == 0) { MBARRIER_INVAL(mbS); MBARRIER_INVAL(mbPV); }
    __syncthreads();
    if (wid == 0) {
        TCGEN05_RELINQUISH();
        TCGEN05_DEALLOC(tmem, 256);
    }

#else
    // fp32 fallback (compile-only)
    float* Qs = (float*)smem;
    float* Ks = Qs + 128 * 65;
    float* Vs = Ks + 64 * 65;
    float* Ps = Vs + 64 * 65;

    const int qb = (int)gridDim.x - 1 - (int)blockIdx.x;
    const int bh = blockIdx.y;
    const int b  = bh / cfg::H;
    const int h  = bh % cfg::H;
    const size_t base = (size_t)bh * cfg::S * cfg::HD;
    const size_t vtb  = (size_t)bh * 64 * 2048;

    const int tid = threadIdx.x;
    const int tx  = tid & 15;
    const int ty  = tid >> 4;

    for (int i = tid; i < 128 * 64; i += 256) {
        int r = i >> 6, c = i & 63;
        size_t off = base + (size_t)(qb * 128 + r) * cfg::HD + c;
        Qs[r * 65 + c] = __bfloat162float(g_Qh[off]) + __bfloat162float(g_Ql[off]);
    }

    float o[8][4];
    float li[8];
#pragma unroll
    for (int i = 0; i < 8; i++) {
        li[i] = 0.f;
#pragma unroll
        for (int j = 0; j < 4; j++) o[i][j] = 0.f;
    }

    const int nkb = 2 * qb + 2;
    for (int kb = 0; kb < nkb; kb++) {
        __syncthreads();
        for (int i = tid; i < 64 * 64; i += 256) {
            int r = i >> 6, c = i & 63;
            size_t off = base + (size_t)(kb * 64 + r) * cfg::HD + c;
            Ks[r * 65 + c] = __bfloat162float(g_Kh[off]) + __bfloat162float(g_Kl[off]);
            Vs[r * 65 + c] = __bfloat162float(g_Vh[off]) + __bfloat162float(g_Vl[off]);
        }
        __syncthreads();

        float s[8][4];
#pragma unroll
        for (int i = 0; i < 8; i++)
#pragma unroll
            for (int j = 0; j < 4; j++) s[i][j] = 0.f;
        for (int d = 0; d < 64; d++) {
            float bk[4];
#pragma unroll
            for (int j = 0; j < 4; j++) bk[j] = Ks[(tx * 4 + j) * 65 + d];
#pragma unroll
            for (int i = 0; i < 8; i++) {
                float aq = Qs[(ty * 8 + i) * 65 + d];
#pragma unroll
                for (int j = 0; j < 4; j++) s[i][j] += aq * bk[j];
            }
        }
#pragma unroll
        for (int i = 0; i < 8; i++) {
            int qgr = qb * 128 + ty * 8 + i;
            float psum = 0.f;
#pragma unroll
            for (int j = 0; j < 4; j++) {
                int kg = kb * 64 + tx * 4 + j;
                float sv = (kg > qgr) ? -1e30f : s[i][j];
                float p = __expf(sv);
                Ps[(ty * 8 + i) * 65 + tx * 4 + j] = p;
                psum += p;
            }
            psum += __shfl_xor_sync(0xffffffffu, psum, 8, 16);
            psum += __shfl_xor_sync(0xffffffffu, psum, 4, 16);
            psum += __shfl_xor_sync(0xffffffffu, psum, 2, 16);
            psum += __shfl_xor_sync(0xffffffffu, psum, 1, 16);
            li[i] += psum;
        }
        __syncwarp();
        for (int c = 0; c < 64; c++) {
            float vv[4];
#pragma unroll
            for (int j = 0; j < 4; j++) vv[j] = Vs[c * 65 + tx * 4 + j];
#pragma unroll
            for (int i = 0; i < 8; i++) {
                float p = Ps[(ty * 8 + i) * 65 + c];
#pragma unroll
                for (int j = 0; j < 4; j++) o[i][j] += p * vv[j];
            }
        }
    }

#pragma unroll
    for (int i = 0; i < 8; i++) {
        int qgr = qb * 128 + ty * 8 + i;
        float e   = __expf(1e-9f);
        float cnt = (float)(cfg::S - 1 - qgr);
        float denom = li[i] + cnt * e;
        float inv = 1.0f / denom;
        size_t ooff = ((size_t)(b * cfg::S + qgr)) * cfg::D + h * cfg::HD + tx * 4;
#pragma unroll
        for (int q = 0; q < 4; q++) {
            float sv = (qgr + 1 < cfg::S)
                     ? g_SV[vtb + (size_t)(tx * 4 + q) * 2048 + qgr + 1] : 0.f;
            float v = (o[i][q] + e * sv) * inv;
            __nv_bfloat16 hh = __float2bfloat16(v);
            g_Ah[ooff + q] = hh;
            g_Al[ooff + q] = __float2bfloat16(v - __bfloat162float(hh));
        }
    }
#endif
}

// ============================================================================
// launcher
// ============================================================================
extern "C" void kernel_launch(void* const* d_in, const int* in_sizes, int n_in,
                              void* d_out, int out_size)
{
    (void)in_sizes; (void)n_in; (void)out_size;
    const float* x      = (const float*)d_in[0];
    const float* w_attn = (const float*)d_in[1];
    const float* b_attn = (const float*)d_in[2];
    const float* w_proj = (const float*)d_in[3];
    const float* b_proj = (const float*)d_in[4];
    float* out = (float*)d_out;

    __nv_bfloat16 *p_xh, *p_xl, *p_ah, *p_al, *p_wah, *p_wal, *p_wph, *p_wpl;
    cudaGetSymbolAddress((void**)&p_xh,  g_Xh);
    cudaGetSymbolAddress((void**)&p_xl,  g_Xl);
    cudaGetSymbolAddress((void**)&p_ah,  g_Ah);
    cudaGetSymbolAddress((void**)&p_al,  g_Al);
    cudaGetSymbolAddress((void**)&p_wah, g_WTah);
    cudaGetSymbolAddress((void**)&p_wal, g_WTal);
    cudaGetSymbolAddress((void**)&p_wph, g_WTph);
    cudaGetSymbolAddress((void**)&p_wpl, g_WTpl);

    cudaFuncSetAttribute(attn_kernel, cudaFuncAttributeMaxDynamicSharedMemorySize,
                         AT_SMEM);
    cudaFuncSetAttribute(gemm_bf16_kernel<true>,
                         cudaFuncAttributeMaxDynamicSharedMemorySize, G3_SMEM);
    cudaFuncSetAttribute(gemm_bf16_kernel<false>,
                         cudaFuncAttributeMaxDynamicSharedMemorySize, G3_SMEM);

    // 0) prep: bf16 split of x; transpose+split weights
    split_x_kernel<<<(cfg::MTOK * cfg::D / 4 + 255) / 256, 256>>>(x);
    transpose_split_kernel<<<dim3(cfg::NQKV / 32, cfg::D / 32), dim3(32, 8)>>>(
        w_attn, p_wah, p_wal, cfg::D, cfg::NQKV);
    transpose_split_kernel<<<dim3(cfg::D / 32, cfg::D / 32), dim3(32, 8)>>>(
        w_proj, p_wph, p_wpl, cfg::D, cfg::D);

    // 1) qkv GEMM (bf16, 2 CTAs/SM) -> Qh/Ql, Kh/Kl, Vh/Vl
    gemm_bf16_kernel<true><<<dim3(cfg::NQKV / 128, cfg::MTOK / 128), 256, G3_SMEM>>>(
        p_xh, p_xl, p_wah, p_wal, b_attn, nullptr, cfg::MTOK, cfg::NQKV, cfg::D);

    // 2) V transpose + fp32 suffix sums
    vt_kernel<<<dim3(cfg::BH, 128), dim3(32, 8)>>>();
    suffix_kernel<<<dim3(cfg::BH, 8), 256>>>();

    // 3) flash attention (bf16, delayed-PV, 2 CTAs/SM)
    attn_kernel<<<dim3(cfg::S / 128, cfg::BH), 256, AT_SMEM>>>();

    // 4) out = A @ w_proj + b_proj
    gemm_bf16_kernel<false><<<dim3(cfg::D / 128, cfg::MTOK / 128), 256, G3_SMEM>>>(
        p_ah, p_al, p_wph, p_wpl, b_proj, out, cfg::MTOK, cfg::D, cfg::D);
}

// round 14
// speedup vs baseline: 1.3420x; 1.3420x over previous
#include <cuda_runtime.h>
#include <cuda_bf16.h>
#include <cstdint>

#if defined(__CUDA_ARCH_FEAT_SM103_ALL) || defined(__CUDA_ARCH_FEAT_SM100_ALL) || \
    defined(__CUDA_ARCH_FEAT_SM101_ALL)
#define TC_OK 1
#else
#define TC_OK 0
#endif

namespace cfg {
constexpr int B  = 4;
constexpr int S  = 2048;
constexpr int D  = 768;
constexpr int H  = 12;
constexpr int HD = 64;
constexpr int MTOK = B * S;       // 8192
constexpr int NQKV = 3 * D;       // 2304
constexpr int BH   = B * H;       // 48
}

// -------- scratch: everything bf16 hi/lo 2-term split --------
__device__ __nv_bfloat16 g_Qh [(size_t)cfg::BH * cfg::S * cfg::HD];
__device__ __nv_bfloat16 g_Ql [(size_t)cfg::BH * cfg::S * cfg::HD];
__device__ __nv_bfloat16 g_Kh [(size_t)cfg::BH * cfg::S * cfg::HD];
__device__ __nv_bfloat16 g_Kl [(size_t)cfg::BH * cfg::S * cfg::HD];
__device__ __nv_bfloat16 g_Vh [(size_t)cfg::BH * cfg::S * cfg::HD];  // [bh][s][d]
__device__ __nv_bfloat16 g_Vl [(size_t)cfg::BH * cfg::S * cfg::HD];
__device__ __nv_bfloat16 g_VTh[(size_t)cfg::BH * cfg::HD * cfg::S];  // [bh][d][s]
__device__ __nv_bfloat16 g_VTl[(size_t)cfg::BH * cfg::HD * cfg::S];
__device__ float         g_SV [(size_t)cfg::BH * cfg::HD * cfg::S];  // fp32 suffix sums
__device__ __nv_bfloat16 g_Ah [(size_t)cfg::MTOK * cfg::D];
__device__ __nv_bfloat16 g_Al [(size_t)cfg::MTOK * cfg::D];
__device__ __nv_bfloat16 g_Xh [(size_t)cfg::MTOK * cfg::D];
__device__ __nv_bfloat16 g_Xl [(size_t)cfg::MTOK * cfg::D];
__device__ __nv_bfloat16 g_WTah[(size_t)cfg::NQKV * cfg::D];
__device__ __nv_bfloat16 g_WTal[(size_t)cfg::NQKV * cfg::D];
__device__ __nv_bfloat16 g_WTph[(size_t)cfg::D * cfg::D];
__device__ __nv_bfloat16 g_WTpl[(size_t)cfg::D * cfg::D];

// ============================================================================
// helpers
// ============================================================================
__device__ __forceinline__ uint32_t smem_to_u32(const void* p) {
    uint32_t a;
    asm("{ .reg .u64 t; cvta.to.shared.u64 t, %1; cvt.u32.u64 %0, t; }"
        : "=r"(a) : "l"(p));
    return a;
}

__device__ __forceinline__ uint32_t pk_bf2(float a, float b) {
    __nv_bfloat162 t;
    t.x = __float2bfloat16(a);
    t.y = __float2bfloat16(b);
    return *(uint32_t*)&t;
}
__device__ __forceinline__ float2 upk_bf2(uint32_t u) {
    __nv_bfloat162 t = *(__nv_bfloat162*)&u;
    return make_float2(__bfloat162float(t.x), __bfloat162float(t.y));
}

#define SMEM_SWIZZLE_128B(off) ((off) ^ (((off) >> 3) & 0x70))
__device__ __forceinline__ uint32_t bf_off(int row, int colb) {
    return SMEM_SWIZZLE_128B((uint32_t)(row * 128 + colb));
}

#if TC_OK
__device__ __forceinline__ uint32_t elect_one_pred() {
    uint32_t pred;
    asm volatile(
        "{\n\t.reg .pred p;\n\telect.sync _|p, 0xFFFFFFFF;\n\t"
        "selp.b32 %0, 1, 0, p;\n\t}"
        : "=r"(pred));
    return pred;
}

#define TCGEN05_ALLOC(a, n) \
    asm volatile("tcgen05.alloc.cta_group::1.sync.aligned.shared::cta.b32 [%0], %1;" \
                 :: "r"((uint32_t)(a)), "r"((uint32_t)(n)) : "memory")
#define TCGEN05_DEALLOC(t, n) \
    asm volatile("tcgen05.dealloc.cta_group::1.sync.aligned.b32 %0, %1;" \
                 :: "r"(t), "r"((uint32_t)(n)))
#define TCGEN05_RELINQUISH() \
    asm volatile("tcgen05.relinquish_alloc_permit.cta_group::1.sync.aligned;")
#define TCGEN05_COMMIT(m) \
    asm volatile("tcgen05.commit.cta_group::1.mbarrier::arrive::one.shared::cluster.b64 [%0];" \
                 :: "r"((uint32_t)(m)) : "memory")
#define TCGEN05_WAIT_LD() asm volatile("tcgen05.wait::ld.sync.aligned;" ::: "memory")
#define TCGEN05_WAIT_ST() asm volatile("tcgen05.wait::st.sync.aligned;" ::: "memory")
#define TCGEN05_FENCE_AFTER()  asm volatile("tcgen05.fence::after_thread_sync;" ::: "memory")
#define TCGEN05_FENCE_BEFORE() asm volatile("tcgen05.fence::before_thread_sync;" ::: "memory")
#define FENCE_PROXY_ASYNC() asm volatile("fence.proxy.async.shared::cta;" ::: "memory")

#define MBARRIER_INIT(m, c) \
    asm volatile("mbarrier.init.shared.b64 [%0], %1;" \
                 :: "r"((uint32_t)(m)), "r"((uint32_t)(c)) : "memory")
#define MBARRIER_INVAL(m) \
    asm volatile("mbarrier.inval.shared.b64 [%0];" :: "r"((uint32_t)(m)) : "memory")

#define MBARRIER_WAIT_PARITY(mbar_addr, phase_parity) do { \
    uint32_t _mbar = (uint32_t)(mbar_addr); \
    uint32_t _parity = (uint32_t)(phase_parity); \
    uint32_t _done; \
    asm volatile( \
        "{\n\t.reg .pred p;\n\t" \
        "mbarrier.try_wait.parity.acquire.cta.shared::cta.b64 p, [%1], %2;\n\t" \
        "selp.b32 %0, 1, 0, p;\n\t}" \
        : "=r"(_done) : "r"(_mbar), "r"(_parity) : "memory"); \
    if (!_done) { \
        asm volatile( \
            "{\n\t.reg .pred P1;\n\t" \
            "WAIT_LOOP_%=:\n\t" \
            "mbarrier.try_wait.parity.acquire.cta.shared::cta.b64 P1, [%0], %1, 0x989680;\n\t" \
            "@P1 bra.uni WAIT_DONE_%=;\n\t" \
            "bra.uni WAIT_LOOP_%=;\n\t" \
            "WAIT_DONE_%=:\n\t}" \
            :: "r"(_mbar), "r"(_parity) : "memory"); \
    } \
} while(0)

#define TCGEN05_LD_32X32B_X32(r, tmem_addr) \
    asm volatile( \
        "tcgen05.ld.sync.aligned.32x32b.x32.b32 " \
        "{%0, %1, %2, %3, %4, %5, %6, %7, " \
        " %8, %9, %10, %11, %12, %13, %14, %15, " \
        " %16, %17, %18, %19, %20, %21, %22, %23, " \
        " %24, %25, %26, %27, %28, %29, %30, %31}, [%32];" \
        : "=r"((r)[0]),  "=r"((r)[1]),  "=r"((r)[2]),  "=r"((r)[3]), \
          "=r"((r)[4]),  "=r"((r)[5]),  "=r"((r)[6]),  "=r"((r)[7]), \
          "=r"((r)[8]),  "=r"((r)[9]),  "=r"((r)[10]), "=r"((r)[11]), \
          "=r"((r)[12]), "=r"((r)[13]), "=r"((r)[14]), "=r"((r)[15]), \
          "=r"((r)[16]), "=r"((r)[17]), "=r"((r)[18]), "=r"((r)[19]), \
          "=r"((r)[20]), "=r"((r)[21]), "=r"((r)[22]), "=r"((r)[23]), \
          "=r"((r)[24]), "=r"((r)[25]), "=r"((r)[26]), "=r"((r)[27]), \
          "=r"((r)[28]), "=r"((r)[29]), "=r"((r)[30]), "=r"((r)[31]) \
        : "r"(tmem_addr))

#define TCGEN05_ST_32X32B_X16(tmem_addr, r) \
    asm volatile( \
        "tcgen05.st.sync.aligned.32x32b.x16.b32 [%0], " \
        "{%1, %2, %3, %4, %5, %6, %7, %8, " \
        " %9, %10, %11, %12, %13, %14, %15, %16};" \
        :: "r"(tmem_addr), \
           "r"((r)[0]),  "r"((r)[1]),  "r"((r)[2]),  "r"((r)[3]), \
           "r"((r)[4]),  "r"((r)[5]),  "r"((r)[6]),  "r"((r)[7]), \
           "r"((r)[8]),  "r"((r)[9]),  "r"((r)[10]), "r"((r)[11]), \
           "r"((r)[12]), "r"((r)[13]), "r"((r)[14]), "r"((r)[15]) \
        : "memory")

static constexpr uint64_t SMEM_DESC_BASE_SW128 =
    (uint64_t(2)  << 61) | (uint64_t(1) << 46) | (uint64_t(64) << 32) | (uint64_t(1) << 16);
#define MAKE_SMEM_DESC(base_addr) \
    (SMEM_DESC_BASE_SW128 | ((uint64_t)((base_addr) >> 4) & 0x3FFF))

__device__ __forceinline__ void mma_bf16_ss(uint32_t d, uint64_t ad, uint64_t bd,
                                            uint32_t idesc, bool acc) {
    uint32_t en = acc ? 1u : 0u;
    asm volatile(
        "{\n\t.reg .pred p;\n\tsetp.ne.u32 p, %5, 0;\n\t"
        "tcgen05.mma.cta_group::1.kind::f16 [%0], %1, %2, %3, {%4, %4, %4, %4}, p;\n\t}"
        :: "r"(d), "l"(ad), "l"(bd), "r"(idesc), "r"(0u), "r"(en)
        : "memory");
}
__device__ __forceinline__ void mma_bf16_ts(uint32_t d, uint32_t a_tmem, uint64_t bd,
                                            uint32_t idesc, bool acc) {
    uint32_t en = acc ? 1u : 0u;
    asm volatile(
        "{\n\t.reg .pred p;\n\tsetp.ne.u32 p, %5, 0;\n\t"
        "tcgen05.mma.cta_group::1.kind::f16 [%0], [%1], %2, %3, {%4, %4, %4, %4}, p;\n\t}"
        :: "r"(d), "r"(a_tmem), "l"(bd), "r"(idesc), "r"(0u), "r"(en)
        : "memory");
}

static constexpr uint32_t IDESC_BF16_128x128 =
    (1u << 4) | (1u << 7) | (1u << 10) | ((128u / 8u) << 17) | ((128u / 16u) << 24);
static constexpr uint32_t IDESC_BF16_128x64 =
    (1u << 4) | (1u << 7) | (1u << 10) | ((64u / 8u) << 17) | ((128u / 16u) << 24);

#define CP_ASYNC16(dst, src) \
    asm volatile("cp.async.cg.shared.global [%0], [%1], 16;" \
                 :: "r"((uint32_t)(dst)), "l"(src) : "memory")
#define CP_COMMIT() asm volatile("cp.async.commit_group;" ::: "memory")
#define CP_WAIT(n)  asm volatile("cp.async.wait_group %0;" :: "n"(n) : "memory")
#endif  // TC_OK

// ============================================================================
// prep: elementwise bf16 hi/lo split of x
// ============================================================================
__global__ void __launch_bounds__(256) split_x_kernel(const float* __restrict__ x)
{
    int i = blockIdx.x * 256 + threadIdx.x;
    if (i >= cfg::MTOK * cfg::D / 4) return;
    float4 v = ((const float4*)x)[i];
    float h0 = __bfloat162float(__float2bfloat16(v.x));
    float h1 = __bfloat162float(__float2bfloat16(v.y));
    float h2 = __bfloat162float(__float2bfloat16(v.z));
    float h3 = __bfloat162float(__float2bfloat16(v.w));
    uint32_t* ph = (uint32_t*)g_Xh;
    uint32_t* pl = (uint32_t*)g_Xl;
    ph[i * 2 + 0] = pk_bf2(h0, h1);
    ph[i * 2 + 1] = pk_bf2(h2, h3);
    pl[i * 2 + 0] = pk_bf2(v.x - h0, v.y - h1);
    pl[i * 2 + 1] = pk_bf2(v.z - h2, v.w - h3);
}

// ============================================================================
// prep: transpose + bf16 split weights
// ============================================================================
__global__ void transpose_split_kernel(const float* __restrict__ in,
                                       __nv_bfloat16* __restrict__ outh,
                                       __nv_bfloat16* __restrict__ outl, int R, int C)
{
    __shared__ float t[32][33];
    int bx = blockIdx.x * 32;
    int by = blockIdx.y * 32;
    int x = bx + threadIdx.x;
#pragma unroll
    for (int j = 0; j < 32; j += 8)
        t[threadIdx.y + j][threadIdx.x] = in[(size_t)(by + threadIdx.y + j) * C + x];
    __syncthreads();
    int x2 = by + threadIdx.x;
#pragma unroll
    for (int j = 0; j < 32; j += 8) {
        float v = t[threadIdx.x][threadIdx.y + j];
        __nv_bfloat16 h = __float2bfloat16(v);
        outh[(size_t)(bx + threadIdx.y + j) * R + x2] = h;
        outl[(size_t)(bx + threadIdx.y + j) * R + x2] =
            __float2bfloat16(v - __bfloat162float(h));
    }
}

// ============================================================================
// V transpose (bf16): g_Vh/g_Vl [bh][s][64] -> g_VTh/g_VTl [bh][d][2048]
// ============================================================================
__global__ void vt_kernel()
{
    __shared__ uint16_t th[32][33], tl[32][33];
    const int bh   = blockIdx.x;
    const int tile = blockIdx.y;
    const int s0 = (tile >> 1) * 32;
    const int d0 = (tile & 1) * 32;
    const size_t vb  = (size_t)bh * cfg::S * cfg::HD;
    const size_t vtb = (size_t)bh * cfg::HD * cfg::S;
#pragma unroll
    for (int j = 0; j < 32; j += 8) {
        size_t off = vb + (size_t)(s0 + threadIdx.y + j) * 64 + d0 + threadIdx.x;
        th[threadIdx.y + j][threadIdx.x] = *(const uint16_t*)&g_Vh[off];
        tl[threadIdx.y + j][threadIdx.x] = *(const uint16_t*)&g_Vl[off];
    }
    __syncthreads();
#pragma unroll
    for (int j = 0; j < 32; j += 8) {
        size_t off = vtb + (size_t)(d0 + threadIdx.y + j) * 2048 + s0 + threadIdx.x;
        *(uint16_t*)&g_VTh[off] = th[threadIdx.x][threadIdx.y + j];
        *(uint16_t*)&g_VTl[off] = tl[threadIdx.x][threadIdx.y + j];
    }
}

// ============================================================================
// GEMM (bf16 2-term, R12 version): C = (Ah+Al)[M,K] @ (Bh+Bl)[N,K]^T + bias
// 128x128 tile, BK=64 (128B rows), 3-stage cp.async pipeline, 256 threads.
// Early permit relinquish after alloc.
// ============================================================================
constexpr int G3_BASE  = 1024;
constexpr int G3_STAGE = 65536;                       // 4 operands x 16KB
constexpr int G3_SMEM  = G3_BASE + 3 * G3_STAGE;      // 197632

template<bool SCATTER>
__global__ void __launch_bounds__(256) gemm_bf16_kernel(
    const __nv_bfloat16* __restrict__ Ah, const __nv_bfloat16* __restrict__ Al,
    const __nv_bfloat16* __restrict__ Bh, const __nv_bfloat16* __restrict__ Bl,
    const float* __restrict__ bias, float* __restrict__ C,
    int M, int N, int K)
{
    extern __shared__ char smem[];
    const int tid = threadIdx.x;
    const int m0  = blockIdx.y * 128;
    const int n0  = blockIdx.x * 128;

#if TC_OK
    const uint32_t smem_base = smem_to_u32(smem);
    const int wid = tid >> 5;
    const int lid = tid & 31;

    if (wid == 0) {
        TCGEN05_ALLOC(smem_base, 128);
        TCGEN05_RELINQUISH();            // free the permit for co-resident CTAs
    }
    if (tid == 0) {
        MBARRIER_INIT(smem_base + 16, 1);
        MBARRIER_INIT(smem_base + 24, 1);
        MBARRIER_INIT(smem_base + 32, 1);
    }
    __syncthreads();
    uint32_t tmem;
    asm volatile("ld.shared.b32 %0, [%1];" : "=r"(tmem) : "r"(smem_base));

    const int T = K / 64;    // 12
    int ph[3] = {0, 0, 0};

    const int row0 = tid >> 3;
    const int e8   = (tid & 7) * 8;
    uint32_t soff[4];
    const __nv_bfloat16 *pAh[4], *pAl[4], *pBh[4], *pBl[4];
#pragma unroll
    for (int i = 0; i < 4; i++) {
        int row = row0 + i * 32;
        soff[i] = bf_off(row, e8 * 2);
        pAh[i] = Ah + (size_t)(m0 + row) * K + e8;
        pAl[i] = Al + (size_t)(m0 + row) * K + e8;
        pBh[i] = Bh + (size_t)(n0 + row) * K + e8;
        pBl[i] = Bl + (size_t)(n0 + row) * K + e8;
    }

    auto cp_tile = [&](uint32_t stage) {
#pragma unroll
        for (int i = 0; i < 4; i++) {
            CP_ASYNC16(stage + soff[i],         pAh[i]);
            CP_ASYNC16(stage + 16384 + soff[i], pAl[i]);
            CP_ASYNC16(stage + 32768 + soff[i], pBh[i]);
            CP_ASYNC16(stage + 49152 + soff[i], pBl[i]);
            pAh[i] += 64; pAl[i] += 64; pBh[i] += 64; pBl[i] += 64;
        }
        CP_COMMIT();
    };

    cp_tile(smem_base + G3_BASE);
    cp_tile(smem_base + G3_BASE + G3_STAGE);

    for (int t = 0; t < T; t++) {
        const int s = t % 3;
        const uint32_t stage = smem_base + G3_BASE + s * G3_STAGE;

        if (t == T - 1) CP_WAIT(0); else CP_WAIT(1);
        __syncthreads();

        if (wid == 0) {
            if (elect_one_pred()) {
                FENCE_PROXY_ASYNC();
                uint64_t dah = MAKE_SMEM_DESC(stage);
                uint64_t dal = MAKE_SMEM_DESC(stage + 16384);
                uint64_t dbh = MAKE_SMEM_DESC(stage + 32768);
                uint64_t dbl = MAKE_SMEM_DESC(stage + 49152);
#pragma unroll
                for (int j = 0; j < 4; j++) {
                    uint64_t oj = (uint64_t)(j * 2);
                    mma_bf16_ss(tmem, dah + oj, dbh + oj, IDESC_BF16_128x128,
                                !(t == 0 && j == 0));
                    mma_bf16_ss(tmem, dal + oj, dbh + oj, IDESC_BF16_128x128, true);
                    mma_bf16_ss(tmem, dah + oj, dbl + oj, IDESC_BF16_128x128, true);
                }
                TCGEN05_COMMIT(smem_base + 16 + 8 * s);
            }
        }

        if (t + 2 < T) {
            const int s2 = (t + 2) % 3;
            if (t >= 1) {
                MBARRIER_WAIT_PARITY(smem_base + 16 + 8 * s2, ph[s2]);
                ph[s2] ^= 1;
            }
            cp_tile(smem_base + G3_BASE + s2 * G3_STAGE);
        }
    }

    {
        const int sl = (T - 1) % 3;
        MBARRIER_WAIT_PARITY(smem_base + 16 + 8 * sl, ph[sl]);
    }
    TCGEN05_FENCE_AFTER();

    float* buf = (float*)(smem + G3_BASE);
    if (wid < 4) {
#pragma unroll
        for (int b = 0; b < 4; b++) {
            uint32_t regs[32];
            TCGEN05_LD_32X32B_X32(regs, tmem + b * 32);
            TCGEN05_WAIT_LD();
            float* row = buf + (size_t)(wid * 32 + lid) * 132 + b * 32;
#pragma unroll
            for (int c = 0; c < 32; c++) row[c] = __uint_as_float(regs[c]);
        }
        TCGEN05_FENCE_BEFORE();
    }
    __syncthreads();

#pragma unroll
    for (int i = 0; i < 16; i++) {
        int g  = tid + i * 256;
        int rr = g >> 5;
        int c4 = (g & 31) * 4;
        const float* row = buf + (size_t)rr * 132 + c4;
        int n = n0 + c4;
        float4 bv = *(const float4*)(bias + n);
        float v0 = row[0] + bv.x, v1 = row[1] + bv.y;
        float v2 = row[2] + bv.z, v3 = row[3] + bv.w;
        int m = m0 + rr;
        if (!SCATTER) {
            float4 v = {v0, v1, v2, v3};
            *(float4*)(C + (size_t)m * N + n) = v;
        } else {
            float h0 = __bfloat162float(__float2bfloat16(v0));
            float h1 = __bfloat162float(__float2bfloat16(v1));
            float h2 = __bfloat162float(__float2bfloat16(v2));
            float h3 = __bfloat162float(__float2bfloat16(v3));
            int part = n / cfg::D;
            int dn   = n - part * cfg::D;
            int hh   = dn >> 6;
            int c    = dn & 63;
            int b_   = m >> 11;
            int s_   = m & 2047;
            __nv_bfloat16* dsth = (part == 0) ? g_Qh : (part == 1) ? g_Kh : g_Vh;
            __nv_bfloat16* dstl = (part == 0) ? g_Ql : (part == 1) ? g_Kl : g_Vl;
            size_t off = ((size_t)(b_ * cfg::H + hh) * cfg::S + s_) * cfg::HD + c;
            uint32_t* dh = (uint32_t*)(dsth + off);
            uint32_t* dl = (uint32_t*)(dstl + off);
            dh[0] = pk_bf2(v0, v1);
            dh[1] = pk_bf2(v2, v3);
            dl[0] = pk_bf2(v0 - h0, v1 - h1);
            dl[1] = pk_bf2(v2 - h2, v3 - h3);
        }
    }

    __syncthreads();
    if (tid == 0) {
        MBARRIER_INVAL(smem_base + 16);
        MBARRIER_INVAL(smem_base + 24);
        MBARRIER_INVAL(smem_base + 32);
    }
    __syncthreads();
    if (wid == 0) {
        TCGEN05_DEALLOC(tmem, 128);
    }

#else
    // fp32 fallback (compile-only): a = Ah+Al etc.
    float* As = (float*)smem;
    float* Bs = As + 8 * 128;
    const int tx = tid & 15;
    const int ty = tid >> 4;
    const int lr = tid >> 1;
    const int lk = (tid & 1) * 4;

    float acc[8][8];
#pragma unroll
    for (int i = 0; i < 8; i++)
#pragma unroll
        for (int j = 0; j < 8; j++) acc[i][j] = 0.f;

    for (int k0 = 0; k0 < K; k0 += 8) {
        __syncthreads();
#pragma unroll
        for (int q = 0; q < 4; q++) {
            size_t ao = (size_t)(m0 + lr) * K + k0 + lk + q;
            size_t bo = (size_t)(n0 + lr) * K + k0 + lk + q;
            As[(lk + q) * 128 + lr] =
                __bfloat162float(Ah[ao]) + __bfloat162float(Al[ao]);
            Bs[(lk + q) * 128 + lr] =
                __bfloat162float(Bh[bo]) + __bfloat162float(Bl[bo]);
        }
        __syncthreads();
#pragma unroll
        for (int kk = 0; kk < 8; kk++) {
            float a[8], b[8];
#pragma unroll
            for (int i = 0; i < 4; i++) {
                a[i]     = As[kk * 128 + ty * 4 + i];
                a[i + 4] = As[kk * 128 + 64 + ty * 4 + i];
                b[i]     = Bs[kk * 128 + tx * 4 + i];
                b[i + 4] = Bs[kk * 128 + 64 + tx * 4 + i];
            }
#pragma unroll
            for (int i = 0; i < 8; i++)
#pragma unroll
                for (int j = 0; j < 8; j++) acc[i][j] += a[i] * b[j];
        }
    }

#pragma unroll
    for (int i = 0; i < 8; i++) {
        int m = m0 + ((i < 4) ? (ty * 4 + i) : (64 + ty * 4 + (i - 4)));
#pragma unroll
        for (int jh = 0; jh < 2; jh++) {
            int n = n0 + jh * 64 + tx * 4;
            float vv[4];
#pragma unroll
            for (int q = 0; q < 4; q++) vv[q] = acc[i][jh * 4 + q] + bias[n + q];
            if (!SCATTER) {
                float4 v = {vv[0], vv[1], vv[2], vv[3]};
                *(float4*)(C + (size_t)m * N + n) = v;
            } else {
                int part = n / cfg::D;
                int dn   = n - part * cfg::D;
                int hh   = dn >> 6;
                int c    = dn & 63;
                int b_   = m >> 11;
                int s_   = m & 2047;
                __nv_bfloat16* dsth = (part == 0) ? g_Qh : (part == 1) ? g_Kh : g_Vh;
                __nv_bfloat16* dstl = (part == 0) ? g_Ql : (part == 1) ? g_Kl : g_Vl;
                size_t off = ((size_t)(b_ * cfg::H + hh) * cfg::S + s_) * cfg::HD + c;
#pragma unroll
                for (int q = 0; q < 4; q++) {
                    __nv_bfloat16 h = __float2bfloat16(vv[q]);
                    dsth[off + q] = h;
                    dstl[off + q] = __float2bfloat16(vv[q] - __bfloat162float(h));
                }
            }
        }
    }
#endif
}

// ============================================================================
// V suffix sums: SV[bh][d][s] = sum_{k>=s} (VTh+VTl)[bh][d][k], fp32
// ============================================================================
__global__ void __launch_bounds__(256) suffix_kernel()
{
    const int bh  = blockIdx.x;
    const int wid = threadIdx.x >> 5;
    const int lid = threadIdx.x & 31;
    const int d   = blockIdx.y * 8 + wid;
    const size_t rb = ((size_t)bh * 64 + d) * 2048;
    const uint4* vh4 = (const uint4*)(g_VTh + rb);
    const uint4* vl4 = (const uint4*)(g_VTl + rb);

    float t = 0.f;
#pragma unroll
    for (int i = 0; i < 8; i++) {
        uint4 a = vh4[lid * 8 + i];
        uint4 b = vl4[lid * 8 + i];
        float2 f;
        f = upk_bf2(a.x); t += f.x + f.y;
        f = upk_bf2(a.y); t += f.x + f.y;
        f = upk_bf2(a.z); t += f.x + f.y;
        f = upk_bf2(a.w); t += f.x + f.y;
        f = upk_bf2(b.x); t += f.x + f.y;
        f = upk_bf2(b.y); t += f.x + f.y;
        f = upk_bf2(b.z); t += f.x + f.y;
        f = upk_bf2(b.w); t += f.x + f.y;
    }
    float s = t;
#pragma unroll
    for (int off = 1; off < 32; off <<= 1) {
        float v = __shfl_down_sync(0xffffffffu, s, off);
        if (lid + off < 32) s += v;
    }
    float add = __shfl_down_sync(0xffffffffu, s, 1);
    if (lid == 31) add = 0.f;

    float acc = add;
    float* svp = g_SV + rb + (size_t)lid * 64;
#pragma unroll
    for (int i = 7; i >= 0; i--) {
        uint4 a = vh4[lid * 8 + i];
        uint4 b = vl4[lid * 8 + i];
        float f[8];
        float2 p;
        p = upk_bf2(a.x); f[0] = p.x; f[1] = p.y;
        p = upk_bf2(a.y); f[2] = p.x; f[3] = p.y;
        p = upk_bf2(a.z); f[4] = p.x; f[5] = p.y;
        p = upk_bf2(a.w); f[6] = p.x; f[7] = p.y;
        p = upk_bf2(b.x); f[0] += p.x; f[1] += p.y;
        p = upk_bf2(b.y); f[2] += p.x; f[3] += p.y;
        p = upk_bf2(b.z); f[4] += p.x; f[5] += p.y;
        p = upk_bf2(b.w); f[6] += p.x; f[7] += p.y;
        float r[8];
#pragma unroll
        for (int j = 7; j >= 0; j--) { acc += f[j]; r[j] = acc; }
        float4 w0 = {r[0], r[1], r[2], r[3]};
        float4 w1 = {r[4], r[5], r[6], r[7]};
        *(float4*)(svp + i * 8)     = w0;
        *(float4*)(svp + i * 8 + 4) = w1;
    }
}

// ============================================================================
// Flash attention (bf16 2-term), DELAYED-PV pipeline, early permit relinquish
// -> genuine 2 CTAs/SM (smem 100352, 256 TMEM cols/CTA).
// ============================================================================
constexpr int AT_LI   = 128;
constexpr int AT_QH   = 2048;
constexpr int AT_QL   = AT_QH + 16384;
constexpr int AT_K0   = AT_QL + 16384;
constexpr int AT_KSTG = 16384;
constexpr int AT_V0   = AT_K0 + 2 * AT_KSTG;
constexpr int AT_VSTG = 16384;
constexpr int AT_SMEM = AT_V0 + 2 * AT_VSTG;          // 100352

__global__ void __launch_bounds__(256) attn_kernel()
{
    extern __shared__ char smem[];
#if TC_OK
    const uint32_t smem_base = smem_to_u32(smem);
    const uint32_t mbS  = smem_base + 8;
    const uint32_t mbPV = smem_base + 16;
    const int tid  = threadIdx.x;
    const int wid  = tid >> 5;
    const int lid  = tid & 31;
    const int subp = wid & 3;
    const int colw = wid >> 2;
    const uint32_t warp_off = (uint32_t)subp << 21;
    const uint32_t coff = (uint32_t)colw * 32u;

    const int qb = (int)gridDim.x - 1 - (int)blockIdx.x;
    const int bh = blockIdx.y;
    const int b  = bh / cfg::H;
    const int h  = bh % cfg::H;
    const size_t base = (size_t)bh * cfg::S * cfg::HD;
    const size_t vtb  = (size_t)bh * 64 * 2048;

    if (wid == 0) {
        TCGEN05_ALLOC(smem_base, 256);
        TCGEN05_RELINQUISH();            // free the permit for co-resident CTAs
    }
    if (tid == 0) { MBARRIER_INIT(mbS, 1); MBARRIER_INIT(mbPV, 1); }
    __syncthreads();
    uint32_t tmem;
    asm volatile("ld.shared.b32 %0, [%1];" : "=r"(tmem) : "r"(smem_base));
    const uint32_t T_S  = tmem;
    const uint32_t T_P0 = tmem + 64;
    const uint32_t T_O  = tmem + 192;

    {
        const __nv_bfloat16* Qhg = g_Qh + base + (size_t)qb * 128 * 64;
        const __nv_bfloat16* Qlg = g_Ql + base + (size_t)qb * 128 * 64;
#pragma unroll
        for (int i = 0; i < 4; i++) {
            int g  = tid + i * 256;
            int r  = g >> 3;
            int e8 = (g & 7) * 8;
            uint32_t off = bf_off(r, e8 * 2);
            *(uint4*)(smem + AT_QH + off) = *(const uint4*)(Qhg + (size_t)r * 64 + e8);
            *(uint4*)(smem + AT_QL + off) = *(const uint4*)(Qlg + (size_t)r * 64 + e8);
        }
    }

    auto load_K = [&](int kb, int ks) {
        const int stage = AT_K0 + ks * AT_KSTG;
        const size_t koff = base + (size_t)kb * 64 * 64;
#pragma unroll
        for (int i = 0; i < 2; i++) {
            int g   = tid + i * 256;
            int key = g >> 3;
            int e8  = (g & 7) * 8;
            uint32_t off = bf_off(key, e8 * 2);
            *(uint4*)(smem + stage + off) =
                *(const uint4*)(g_Kh + koff + (size_t)key * 64 + e8);
            *(uint4*)(smem + stage + 8192 + off) =
                *(const uint4*)(g_Kl + koff + (size_t)key * 64 + e8);
        }
    };
    auto load_V = [&](int kb, int vs) {
        const int stage = AT_V0 + vs * AT_VSTG;
        const size_t voff = vtb + (size_t)kb * 64;
#pragma unroll
        for (int i = 0; i < 2; i++) {
            int g  = tid + i * 256;
            int d  = g >> 3;
            int e8 = (g & 7) * 8;
            uint32_t off = bf_off(d, e8 * 2);
            *(uint4*)(smem + stage + off) =
                *(const uint4*)(g_VTh + voff + (size_t)d * 2048 + e8);
            *(uint4*)(smem + stage + 8192 + off) =
                *(const uint4*)(g_VTl + voff + (size_t)d * 2048 + e8);
        }
    };

    const int nkb = 2 * qb + 2;

    auto issue_S = [&](int ks) {
        const uint32_t stage = smem_base + AT_K0 + ks * AT_KSTG;
        uint64_t dqh = MAKE_SMEM_DESC(smem_base + AT_QH);
        uint64_t dql = MAKE_SMEM_DESC(smem_base + AT_QL);
        uint64_t dkh = MAKE_SMEM_DESC(stage);
        uint64_t dkl = MAKE_SMEM_DESC(stage + 8192);
#pragma unroll
        for (int j = 0; j < 4; j++) {
            uint64_t oj = (uint64_t)(j * 2);
            mma_bf16_ss(T_S, dqh + oj, dkh + oj, IDESC_BF16_128x64, j != 0);
            mma_bf16_ss(T_S, dql + oj, dkh + oj, IDESC_BF16_128x64, true);
            mma_bf16_ss(T_S, dqh + oj, dkl + oj, IDESC_BF16_128x64, true);
        }
    };
    auto issue_PV = [&](int pvkb, bool acc) {
        const uint32_t T_PH = T_P0 + (uint32_t)(pvkb & 1) * 64u;
        const uint32_t T_PL = T_PH + 32u;
        const uint32_t stage = smem_base + AT_V0 + (pvkb & 1) * AT_VSTG;
        uint64_t dvh = MAKE_SMEM_DESC(stage);
        uint64_t dvl = MAKE_SMEM_DESC(stage + 8192);
#pragma unroll
        for (int j = 0; j < 4; j++) {
            uint64_t vo = (uint64_t)(j * 2);
            uint32_t ao = (uint32_t)(j * 8);
            mma_bf16_ts(T_O, T_PH + ao, dvh + vo, IDESC_BF16_128x64, acc || j != 0);
            mma_bf16_ts(T_O, T_PL + ao, dvh + vo, IDESC_BF16_128x64, true);
            mma_bf16_ts(T_O, T_PH + ao, dvl + vo, IDESC_BF16_128x64, true);
        }
    };

    load_K(0, 0);
    if (nkb > 1) load_K(1, 1);
    load_V(0, 0);
    __syncthreads();
    if (wid == 0) {
        if (elect_one_pred()) {
            FENCE_PROXY_ASYNC();
            issue_S(0);
            TCGEN05_COMMIT(mbS);
        }
    }

    float li = 0.f;
    const int qg = qb * 128 + subp * 32 + lid;
    int phS = 0, phPV = 0;

    for (int kb = 0; kb < nkb; kb++) {
        MBARRIER_WAIT_PARITY(mbS, phS); phS ^= 1;
        TCGEN05_FENCE_AFTER();

        uint32_t su[32];
        TCGEN05_LD_32X32B_X32(su, T_S + coff + warp_off);
        TCGEN05_WAIT_LD();
        __syncthreads();

        if (wid == 0) {
            TCGEN05_FENCE_AFTER();
            if (elect_one_pred()) {
                FENCE_PROXY_ASYNC();
                if (kb > 0) {
                    issue_PV(kb - 1, kb > 1);
                    TCGEN05_COMMIT(mbPV);
                }
                if (kb + 1 < nkb) {
                    issue_S((kb + 1) & 1);
                    TCGEN05_COMMIT(mbS);
                }
            }
        }

        const uint32_t T_PH = T_P0 + (uint32_t)(kb & 1) * 64u;
        const uint32_t T_PL = T_PH + 32u;
        const int kg0 = kb * 64 + colw * 32;
        const bool diag = (kg0 + 31 > qg);
        float ps = 0.f;
        uint32_t phv[16], plv[16];
#pragma unroll
        for (int j = 0; j < 16; j++) {
            float s0 = __uint_as_float(su[2 * j]);
            float s1 = __uint_as_float(su[2 * j + 1]);
            if (diag) {
                if (kg0 + 2 * j     > qg) s0 = -1e30f;
                if (kg0 + 2 * j + 1 > qg) s1 = -1e30f;
            }
            float p0 = __expf(s0);
            float p1 = __expf(s1);
            ps += p0 + p1;
            float h0 = __bfloat162float(__float2bfloat16(p0));
            float h1 = __bfloat162float(__float2bfloat16(p1));
            phv[j] = pk_bf2(p0, p1);
            plv[j] = pk_bf2(p0 - h0, p1 - h1);
        }
        TCGEN05_ST_32X32B_X16(T_PH + (uint32_t)colw * 16u + warp_off, phv);
        TCGEN05_ST_32X32B_X16(T_PL + (uint32_t)colw * 16u + warp_off, plv);
        TCGEN05_WAIT_ST();
        li += ps;
        TCGEN05_FENCE_BEFORE();

        if (kb + 2 < nkb) load_K(kb + 2, kb & 1);

        if (kb > 0) { MBARRIER_WAIT_PARITY(mbPV, phPV); phPV ^= 1; }
        if (kb + 1 < nkb) load_V(kb + 1, (kb + 1) & 1);
    }

    __syncthreads();
    if (wid == 0) {
        TCGEN05_FENCE_AFTER();
        if (elect_one_pred()) {
            FENCE_PROXY_ASYNC();
            issue_PV(nkb - 1, true);
            TCGEN05_COMMIT(mbPV);
        }
    }
    MBARRIER_WAIT_PARITY(mbPV, phPV);
    TCGEN05_FENCE_AFTER();

    {
        float* sli = (float*)(smem + AT_LI);
        const int rix = subp * 32 + lid;
        sli[rix * 2 + colw] = li;
        __syncthreads();
        float litot = li + sli[rix * 2 + (colw ^ 1)];

        uint32_t ov[32];
        TCGEN05_LD_32X32B_X32(ov, T_O + coff + warp_off);
        TCGEN05_WAIT_LD();

        float e   = __expf(1e-9f);
        float cnt = (float)(cfg::S - 1 - qg);
        float inv = 1.0f / (litot + cnt * e);
        size_t ooff = ((size_t)(b * cfg::S + qg)) * cfg::D + h * cfg::HD + colw * 32;
        const bool has = (qg + 1 < cfg::S);
        uint32_t* oh = (uint32_t*)(g_Ah + ooff);
        uint32_t* ol = (uint32_t*)(g_Al + ooff);
#pragma unroll
        for (int c2 = 0; c2 < 16; c2++) {
            int d0 = colw * 32 + c2 * 2;
            float sv0 = has ? g_SV[vtb + (size_t)(d0 + 0) * 2048 + qg + 1] : 0.f;
            float sv1 = has ? g_SV[vtb + (size_t)(d0 + 1) * 2048 + qg + 1] : 0.f;
            float v0 = (__uint_as_float(ov[c2 * 2])     + e * sv0) * inv;
            float v1 = (__uint_as_float(ov[c2 * 2 + 1]) + e * sv1) * inv;
            float h0 = __bfloat162float(__float2bfloat16(v0));
            float h1 = __bfloat162float(__float2bfloat16(v1));
            oh[c2] = pk_bf2(v0, v1);
            ol[c2] = pk_bf2(v0 - h0, v1 - h1);
        }
    }

    __syncthreads();
    if (tid == 0) { MBARRIER_INVAL(mbS); MBARRIER_INVAL(mbPV); }
    __syncthreads();
    if (wid == 0) {
        TCGEN05_DEALLOC(tmem, 256);
    }

#else
    // fp32 fallback (compile-only)
    float* Qs = (float*)smem;
    float* Ks = Qs + 128 * 65;
    float* Vs = Ks + 64 * 65;
    float* Ps = Vs + 64 * 65;

    const int qb = (int)gridDim.x - 1 - (int)blockIdx.x;
    const int bh = blockIdx.y;
    const int b  = bh / cfg::H;
    const int h  = bh % cfg::H;
    const size_t base = (size_t)bh * cfg::S * cfg::HD;
    const size_t vtb  = (size_t)bh * 64 * 2048;

    const int tid = threadIdx.x;
    const int tx  = tid & 15;
    const int ty  = tid >> 4;

    for (int i = tid; i < 128 * 64; i += 256) {
        int r = i >> 6, c = i & 63;
        size_t off = base + (size_t)(qb * 128 + r) * cfg::HD + c;
        Qs[r * 65 + c] = __bfloat162float(g_Qh[off]) + __bfloat162float(g_Ql[off]);
    }

    float o[8][4];
    float li[8];
#pragma unroll
    for (int i = 0; i < 8; i++) {
        li[i] = 0.f;
#pragma unroll
        for (int j = 0; j < 4; j++) o[i][j] = 0.f;
    }

    const int nkb = 2 * qb + 2;
    for (int kb = 0; kb < nkb; kb++) {
        __syncthreads();
        for (int i = tid; i < 64 * 64; i += 256) {
            int r = i >> 6, c = i & 63;
            size_t off = base + (size_t)(kb * 64 + r) * cfg::HD + c;
            Ks[r * 65 + c] = __bfloat162float(g_Kh[off]) + __bfloat162float(g_Kl[off]);
            Vs[r * 65 + c] = __bfloat162float(g_Vh[off]) + __bfloat162float(g_Vl[off]);
        }
        __syncthreads();

        float s[8][4];
#pragma unroll
        for (int i = 0; i < 8; i++)
#pragma unroll
            for (int j = 0; j < 4; j++) s[i][j] = 0.f;
        for (int d = 0; d < 64; d++) {
            float bk[4];
#pragma unroll
            for (int j = 0; j < 4; j++) bk[j] = Ks[(tx * 4 + j) * 65 + d];
#pragma unroll
            for (int i = 0; i < 8; i++) {
                float aq = Qs[(ty * 8 + i) * 65 + d];
#pragma unroll
                for (int j = 0; j < 4; j++) s[i][j] += aq * bk[j];
            }
        }
#pragma unroll
        for (int i = 0; i < 8; i++) {
            int qgr = qb * 128 + ty * 8 + i;
            float psum = 0.f;
#pragma unroll
            for (int j = 0; j < 4; j++) {
                int kg = kb * 64 + tx * 4 + j;
                float sv = (kg > qgr) ? -1e30f : s[i][j];
                float p = __expf(sv);
                Ps[(ty * 8 + i) * 65 + tx * 4 + j] = p;
                psum += p;
            }
            psum += __shfl_xor_sync(0xffffffffu, psum, 8, 16);
            psum += __shfl_xor_sync(0xffffffffu, psum, 4, 16);
            psum += __shfl_xor_sync(0xffffffffu, psum, 2, 16);
            psum += __shfl_xor_sync(0xffffffffu, psum, 1, 16);
            li[i] += psum;
        }
        __syncwarp();
        for (int c = 0; c < 64; c++) {
            float vv[4];
#pragma unroll
            for (int j = 0; j < 4; j++) vv[j] = Vs[c * 65 + tx * 4 + j];
#pragma unroll
            for (int i = 0; i < 8; i++) {
                float p = Ps[(ty * 8 + i) * 65 + c];
#pragma unroll
                for (int j = 0; j < 4; j++) o[i][j] += p * vv[j];
            }
        }
    }

#pragma unroll
    for (int i = 0; i < 8; i++) {
        int qgr = qb * 128 + ty * 8 + i;
        float e   = __expf(1e-9f);
        float cnt = (float)(cfg::S - 1 - qgr);
        float denom = li[i] + cnt * e;
        float inv = 1.0f / denom;
        size_t ooff = ((size_t)(b * cfg::S + qgr)) * cfg::D + h * cfg::HD + tx * 4;
#pragma unroll
        for (int q = 0; q < 4; q++) {
            float sv = (qgr + 1 < cfg::S)
                     ? g_SV[vtb + (size_t)(tx * 4 + q) * 2048 + qgr + 1] : 0.f;
            float v = (o[i][q] + e * sv) * inv;
            __nv_bfloat16 hh = __float2bfloat16(v);
            g_Ah[ooff + q] = hh;
            g_Al[ooff + q] = __float2bfloat16(v - __bfloat162float(hh));
        }
    }
#endif
}

// ============================================================================
// launcher
// ============================================================================
extern "C" void kernel_launch(void* const* d_in, const int* in_sizes, int n_in,
                              void* d_out, int out_size)
{
    (void)in_sizes; (void)n_in; (void)out_size;
    const float* x      = (const float*)d_in[0];
    const float* w_attn = (const float*)d_in[1];
    const float* b_attn = (const float*)d_in[2];
    const float* w_proj = (const float*)d_in[3];
    const float* b_proj = (const float*)d_in[4];
    float* out = (float*)d_out;

    __nv_bfloat16 *p_xh, *p_xl, *p_ah, *p_al, *p_wah, *p_wal, *p_wph, *p_wpl;
    cudaGetSymbolAddress((void**)&p_xh,  g_Xh);
    cudaGetSymbolAddress((void**)&p_xl,  g_Xl);
    cudaGetSymbolAddress((void**)&p_ah,  g_Ah);
    cudaGetSymbolAddress((void**)&p_al,  g_Al);
    cudaGetSymbolAddress((void**)&p_wah, g_WTah);
    cudaGetSymbolAddress((void**)&p_wal, g_WTal);
    cudaGetSymbolAddress((void**)&p_wph, g_WTph);
    cudaGetSymbolAddress((void**)&p_wpl, g_WTpl);

    cudaFuncSetAttribute(attn_kernel, cudaFuncAttributeMaxDynamicSharedMemorySize,
                         AT_SMEM);
    cudaFuncSetAttribute(gemm_bf16_kernel<true>,
                         cudaFuncAttributeMaxDynamicSharedMemorySize, G3_SMEM);
    cudaFuncSetAttribute(gemm_bf16_kernel<false>,
                         cudaFuncAttributeMaxDynamicSharedMemorySize, G3_SMEM);

    // 0) prep: bf16 split of x; transpose+split weights
    split_x_kernel<<<(cfg::MTOK * cfg::D / 4 + 255) / 256, 256>>>(x);
    transpose_split_kernel<<<dim3(cfg::NQKV / 32, cfg::D / 32), dim3(32, 8)>>>(
        w_attn, p_wah, p_wal, cfg::D, cfg::NQKV);
    transpose_split_kernel<<<dim3(cfg::D / 32, cfg::D / 32), dim3(32, 8)>>>(
        w_proj, p_wph, p_wpl, cfg::D, cfg::D);

    // 1) qkv GEMM (bf16, R12 config) -> Qh/Ql, Kh/Kl, Vh/Vl
    gemm_bf16_kernel<true><<<dim3(cfg::NQKV / 128, cfg::MTOK / 128), 256, G3_SMEM>>>(
        p_xh, p_xl, p_wah, p_wal, b_attn, nullptr, cfg::MTOK, cfg::NQKV, cfg::D);

    // 2) V transpose + fp32 suffix sums
    vt_kernel<<<dim3(cfg::BH, 128), dim3(32, 8)>>>();
    suffix_kernel<<<dim3(cfg::BH, 8), 256>>>();

    // 3) flash attention (bf16, delayed-PV, early permit relinquish)
    attn_kernel<<<dim3(cfg::S / 128, cfg::BH), 256, AT_SMEM>>>();

    // 4) out = A @ w_proj + b_proj
    gemm_bf16_kernel<false><<<dim3(cfg::D / 128, cfg::MTOK / 128), 256, G3_SMEM>>>(
        p_ah, p_al, p_wph, p_wpl, b_proj, out, cfg::MTOK, cfg::D, cfg::D);
}